// round 1
// baseline (speedup 1.0000x reference)
#include <cuda_runtime.h>
#include <math.h>

#define BB   4
#define TT   1024
#define FEATC 512
#define HH   8
#define DKc  64
#define SPANC 100
#define PADL 50
#define TQ   32
#define KR   (TQ + SPANC - 1)   /* 131 */
#define KSTR 68                 /* padded row stride (floats), 17 float4 */

// -------- scratch (device globals; no runtime allocation) --------
__device__ float g_q[BB*TT*FEATC];
__device__ float g_k[BB*TT*FEATC];
__device__ float g_v[BB*TT*FEATC];
__device__ float g_x[BB*TT*FEATC];

// ---------------- 64x64x16 SGEMM body, 4x4 micro-tile ----------------
__device__ __forceinline__ void sgemm64(const float* __restrict__ A,
                                        const float* __restrict__ W,
                                        const float* __restrict__ bias,
                                        float* __restrict__ C)
{
    __shared__ float As[16*68];   // transposed A tile, padded stride 68
    __shared__ float Bs[16*64];

    const int tid = threadIdx.x;
    const int m0 = blockIdx.y * 64;
    const int n0 = blockIdx.x * 64;
    const int tx = tid & 15, ty = tid >> 4;
    const int aRow = tid >> 2, aK = (tid & 3) << 2;
    const int bRow = tid >> 4, bCol = (tid & 15) << 2;

    float acc[4][4];
#pragma unroll
    for (int i = 0; i < 4; i++)
#pragma unroll
        for (int j = 0; j < 4; j++) acc[i][j] = 0.f;

    for (int k0 = 0; k0 < FEATC; k0 += 16) {
        float4 av = *(const float4*)&A[(size_t)(m0 + aRow) * FEATC + k0 + aK];
        float4 bv = *(const float4*)&W[(size_t)(k0 + bRow) * FEATC + n0 + bCol];
        __syncthreads();
        As[(aK + 0) * 68 + aRow] = av.x;
        As[(aK + 1) * 68 + aRow] = av.y;
        As[(aK + 2) * 68 + aRow] = av.z;
        As[(aK + 3) * 68 + aRow] = av.w;
        *(float4*)&Bs[bRow * 64 + bCol] = bv;
        __syncthreads();
#pragma unroll
        for (int kk = 0; kk < 16; kk++) {
            float a_[4], b_[4];
            *(float4*)a_ = *(const float4*)&As[kk * 68 + ty * 4];
            *(float4*)b_ = *(const float4*)&Bs[kk * 64 + tx * 4];
#pragma unroll
            for (int i = 0; i < 4; i++)
#pragma unroll
                for (int j = 0; j < 4; j++)
                    acc[i][j] = fmaf(a_[i], b_[j], acc[i][j]);
        }
    }

    float bvl[4];
    *(float4*)bvl = *(const float4*)&bias[n0 + tx * 4];
#pragma unroll
    for (int i = 0; i < 4; i++) {
        int row = m0 + ty * 4 + i;
        float4 o;
        o.x = acc[i][0] + bvl[0];
        o.y = acc[i][1] + bvl[1];
        o.z = acc[i][2] + bvl[2];
        o.w = acc[i][3] + bvl[3];
        *(float4*)&C[(size_t)row * FEATC + n0 + tx * 4] = o;
    }
}

__global__ void qkv_gemm(const float* __restrict__ Q, const float* __restrict__ K,
                         const float* __restrict__ V,
                         const float* __restrict__ Wq, const float* __restrict__ Wk,
                         const float* __restrict__ Wv,
                         const float* __restrict__ bq, const float* __restrict__ bk,
                         const float* __restrict__ bv)
{
    const int z = blockIdx.z;
    const float* A  = (z == 0) ? Q  : (z == 1) ? K  : V;
    const float* W  = (z == 0) ? Wq : (z == 1) ? Wk : Wv;
    const float* bi = (z == 0) ? bq : (z == 1) ? bk : bv;
    float*       C  = (z == 0) ? g_q : (z == 1) ? g_k : g_v;
    sgemm64(A, W, bi, C);
}

__global__ void out_gemm(const float* __restrict__ Wo, const float* __restrict__ bo,
                         float* __restrict__ out)
{
    sgemm64(g_x, Wo, bo, out);
}

// ---------------- banded attention with adaptive soft span ----------------
// grid: (TT/TQ, BB*HH), block: 256 (8 warps, warp = 1 query at a time, 4 each)
__global__ void attn_kernel(const int* __restrict__ mask, const float* __restrict__ span)
{
    extern __shared__ float sm[];
    float* Ks = sm;                    // KR*KSTR
    float* Vs = Ks + KR * KSTR;        // KR*KSTR
    float* Qs = Vs + KR * KSTR;        // 8*64
    float* Ws = Qs + 8 * 64;           // 8*SPANC
    int*   Ms = (int*)(Ws + 8 * SPANC); // KR

    const int tid  = threadIdx.x;
    const int w    = tid >> 5;
    const int lane = tid & 31;
    const int bh = blockIdx.y;
    const int b = bh >> 3, h = bh & 7;
    const int t0 = blockIdx.x * TQ;
    const int j0 = t0 - PADL;

    const size_t baseHB = (size_t)b * TT * FEATC + h * DKc;

    // stage K/V window (zero-fill OOB rows) + mask band
    for (int idx = tid; idx < KR * DKc; idx += 256) {
        int r = idx >> 6, d = idx & 63;
        int j = j0 + r;
        float kv = 0.f, vv = 0.f;
        if (j >= 0 && j < TT) {
            kv = g_k[baseHB + (size_t)j * FEATC + d];
            vv = g_v[baseHB + (size_t)j * FEATC + d];
        }
        Ks[r * KSTR + d] = kv;
        Vs[r * KSTR + d] = vv;
    }
    for (int idx = tid; idx < KR; idx += 256) {
        int j = j0 + idx;
        Ms[idx] = (j >= 0 && j < TT) ? mask[b * TT + j] : 0;
    }
    __syncthreads();

    const float sp = span[h];
    const float4* K4 = (const float4*)Ks;

    for (int qi = 0; qi < 4; qi++) {
        const int t = t0 + w * 4 + qi;
        const int qloc = t - t0;

        // load q into per-warp smem
        Qs[w * 64 + lane]      = g_q[baseHB + (size_t)t * FEATC + lane];
        Qs[w * 64 + 32 + lane] = g_q[baseHB + (size_t)t * FEATC + 32 + lane];
        __syncwarp();

        const int s0 = lane, s1 = lane + 32, s2 = lane + 64, s3 = lane + 96;
        const int r0 = qloc + s0, r1 = qloc + s1, r2 = qloc + s2;
        const bool ok3 = (s3 < SPANC);
        const int r3 = ok3 ? (qloc + s3) : r0;

        const float4* Q4  = (const float4*)(Qs + w * 64);
        const float4* pk0 = K4 + r0 * 17;
        const float4* pk1 = K4 + r1 * 17;
        const float4* pk2 = K4 + r2 * 17;
        const float4* pk3 = K4 + r3 * 17;

        float acc0 = 0.f, acc1 = 0.f, acc2 = 0.f, acc3 = 0.f;
#pragma unroll
        for (int d4 = 0; d4 < 16; d4++) {
            float4 q = Q4[d4];
            float4 k0v = pk0[d4];
            float4 k1v = pk1[d4];
            float4 k2v = pk2[d4];
            float4 k3v = pk3[d4];
            acc0 = fmaf(q.x, k0v.x, fmaf(q.y, k0v.y, fmaf(q.z, k0v.z, fmaf(q.w, k0v.w, acc0))));
            acc1 = fmaf(q.x, k1v.x, fmaf(q.y, k1v.y, fmaf(q.z, k1v.z, fmaf(q.w, k1v.w, acc1))));
            acc2 = fmaf(q.x, k2v.x, fmaf(q.y, k2v.y, fmaf(q.z, k2v.z, fmaf(q.w, k2v.w, acc2))));
            acc3 = fmaf(q.x, k3v.x, fmaf(q.y, k3v.y, fmaf(q.z, k3v.z, fmaf(q.w, k3v.w, acc3))));
        }

        const float scale = 0.125f;  // 1/sqrt(64)
        const bool v0 = Ms[r0] != 0;
        const bool v1 = Ms[r1] != 0;
        const bool v2 = Ms[r2] != 0;
        const bool v3 = ok3 && (Ms[r3] != 0);
        float sc0 = acc0 * scale, sc1 = acc1 * scale, sc2 = acc2 * scale, sc3 = acc3 * scale;

        float x0 = v0 ? sc0 : -1e30f;
        float x1 = v1 ? sc1 : -1e30f;
        float x2 = v2 ? sc2 : -1e30f;
        float x3 = v3 ? sc3 : -1e30f;
        float mx = fmaxf(fmaxf(x0, x1), fmaxf(x2, x3));
#pragma unroll
        for (int o = 16; o; o >>= 1) mx = fmaxf(mx, __shfl_xor_sync(0xffffffffu, mx, o));

        float e0 = v0 ? __expf(sc0 - mx) : 0.f;
        float e1 = v1 ? __expf(sc1 - mx) : 0.f;
        float e2 = v2 ? __expf(sc2 - mx) : 0.f;
        float e3 = v3 ? __expf(sc3 - mx) : 0.f;

        // soft span mask: clip(((s-99) + span*100)/2 + 1, 0, 1)
        float so0 = fminf(fmaxf(((float)(s0 - 99) + sp * 100.f) * 0.5f + 1.f, 0.f), 1.f);
        float so1 = fminf(fmaxf(((float)(s1 - 99) + sp * 100.f) * 0.5f + 1.f, 0.f), 1.f);
        float so2 = fminf(fmaxf(((float)(s2 - 99) + sp * 100.f) * 0.5f + 1.f, 0.f), 1.f);
        float so3 = fminf(fmaxf(((float)(s3 - 99) + sp * 100.f) * 0.5f + 1.f, 0.f), 1.f);

        float a0 = e0 * so0, a1 = e1 * so1, a2 = e2 * so2, a3 = e3 * so3;
        float E  = e0 + e1 + e2 + e3;
        float Sa = a0 + a1 + a2 + a3;
#pragma unroll
        for (int o = 16; o; o >>= 1) {
            E  += __shfl_xor_sync(0xffffffffu, E,  o);
            Sa += __shfl_xor_sync(0xffffffffu, Sa, o);
        }
        // final weight: a_i / (Sa + 1e-8*E)  ==  (a_i/E) / (Sa/E + 1e-8)
        const float inv = 1.f / (Sa + 1e-8f * E);

        Ws[w * SPANC + s0] = a0 * inv;
        Ws[w * SPANC + s1] = a1 * inv;
        Ws[w * SPANC + s2] = a2 * inv;
        if (ok3) Ws[w * SPANC + s3] = a3 * inv;
        __syncwarp();

        // PV: lanes split DK
        float o0 = 0.f, o1 = 0.f;
        const float* wrow = Ws + w * SPANC;
        const float* vrow = Vs + qloc * KSTR;
#pragma unroll 4
        for (int s = 0; s < SPANC; s++) {
            float wt = wrow[s];
            o0 = fmaf(wt, vrow[s * KSTR + lane], o0);
            o1 = fmaf(wt, vrow[s * KSTR + 32 + lane], o1);
        }
        g_x[baseHB + (size_t)t * FEATC + lane]      = o0;
        g_x[baseHB + (size_t)t * FEATC + 32 + lane] = o1;
        __syncwarp();
    }
}

// ---------------- launch ----------------
extern "C" void kernel_launch(void* const* d_in, const int* in_sizes, int n_in,
                              void* d_out, int out_size)
{
    const float* query = (const float*)d_in[0];
    const float* key   = (const float*)d_in[1];
    const float* value = (const float*)d_in[2];
    const int*   mask  = (const int*)d_in[3];
    const float* Wq    = (const float*)d_in[4];
    const float* bq    = (const float*)d_in[5];
    const float* Wk    = (const float*)d_in[6];
    const float* bk    = (const float*)d_in[7];
    const float* Wv    = (const float*)d_in[8];
    const float* bv    = (const float*)d_in[9];
    const float* Wo    = (const float*)d_in[10];
    const float* bo    = (const float*)d_in[11];
    const float* span  = (const float*)d_in[12];
    float* out = (float*)d_out;

    // 3 QKV projections in one launch (z selects)
    dim3 gq(FEATC / 64, (BB * TT) / 64, 3);
    qkv_gemm<<<gq, 256>>>(query, key, value, Wq, Wk, Wv, bq, bk, bv);

    // banded attention
    size_t smem = (size_t)(2 * KR * KSTR + 8 * 64 + 8 * SPANC) * sizeof(float)
                + (size_t)KR * sizeof(int);
    cudaFuncSetAttribute(attn_kernel, cudaFuncAttributeMaxDynamicSharedMemorySize, (int)smem);
    attn_kernel<<<dim3(TT / TQ, BB * HH), 256, smem>>>(mask, span);

    // output projection
    out_gemm<<<dim3(FEATC / 64, (BB * TT) / 64), 256>>>(Wo, bo, out);
}

// round 6
// speedup vs baseline: 1.2247x; 1.2247x over previous
#include <cuda_runtime.h>
#include <math.h>
#include <stdint.h>

#define BB    4
#define TT    1024
#define FEATC 512
#define HH    8
#define DKc   64
#define SPANC 100
#define PADL  50
#define TQ    32
#define KR    (TQ + SPANC - 1)   /* 131 */
#define KSTR  68                 /* padded row stride (floats) */

// -------- scratch (device globals; no runtime allocation) --------
__device__ float g_q[BB*TT*FEATC];
__device__ float g_k[BB*TT*FEATC];
__device__ float g_v[BB*TT*FEATC];
__device__ float g_x[BB*TT*FEATC];

// ======================= helpers =======================
__device__ __forceinline__ uint32_t smem_to_u32(const void* p) {
    uint32_t a;
    asm("{ .reg .u64 t; cvta.to.shared.u64 t, %1; cvt.u32.u64 %0, t; }" : "=r"(a) : "l"(p));
    return a;
}
__device__ __forceinline__ void cp_async16(uint32_t dst, const void* src) {
    asm volatile("cp.async.cg.shared.global [%0], [%1], 16;" :: "r"(dst), "l"(src));
}
#define CP_COMMIT() asm volatile("cp.async.commit_group;" ::: "memory")
#define CP_WAIT(n)  asm volatile("cp.async.wait_group %0;" :: "n"(n) : "memory")

__device__ __forceinline__ float tf32_rna(float x) {
    float r;
    asm("cvt.rna.tf32.f32 %0, %1;" : "=f"(r) : "f"(x));
    return r;
}

// D(16x8) += A(16x8) * B(8x8), tf32 inputs, fp32 accum. row.col.
__device__ __forceinline__ void mma8(float* c, const uint32_t* a, const uint32_t* b) {
    asm volatile(
        "mma.sync.aligned.m16n8k8.row.col.f32.tf32.tf32.f32 "
        "{%0,%1,%2,%3},{%4,%5,%6,%7},{%8,%9},{%0,%1,%2,%3};"
        : "+f"(c[0]), "+f"(c[1]), "+f"(c[2]), "+f"(c[3])
        : "r"(a[0]), "r"(a[1]), "r"(a[2]), "r"(a[3]), "r"(b[0]), "r"(b[1]));
}

// ================= 3xTF32 mma.sync GEMM: C[M,512] = A[M,512] @ W[512,512] + bias =================
// tile 128x128, BK=16, 8 warps (2x4), warp tile 64x32, cp.async double buffer
#define BKt   16
#define ASTR  20     /* A smem stride (floats), conflict-free for 8x4 frag pattern */
#define BSTR  136    /* B smem stride (floats), conflict-free for 4x8 frag pattern */
#define ABYTES (128 * ASTR * 4)   /* 10240 */
#define BBYTES (BKt * BSTR * 4)   /*  8704 */
#define BUF_FLOATS ((ABYTES + BBYTES) / 4)

__device__ __forceinline__ void gemm_prefetch(const float* __restrict__ A,
                                              const float* __restrict__ W,
                                              int m0, int n0, int s,
                                              uint32_t Abase, uint32_t Bbase, int tid)
{
    const float* Ag = A + (size_t)m0 * FEATC + s * BKt;
    const float* Bg = W + (size_t)(s * BKt) * FEATC + n0;
#pragma unroll
    for (int i = 0; i < 2; i++) {
        int q = tid + i * 256;
        int ar = q >> 2, ac4 = q & 3;                   // A: 128 rows x 4 f4-chunks
        cp_async16(Abase + (uint32_t)(ar * ASTR + ac4 * 4) * 4,
                   Ag + (size_t)ar * FEATC + ac4 * 4);
        int br = q >> 5, bn4 = q & 31;                  // B: 16 rows x 32 f4-chunks
        cp_async16(Bbase + (uint32_t)(br * BSTR + bn4 * 4) * 4,
                   Bg + (size_t)br * FEATC + bn4 * 4);
    }
    CP_COMMIT();
}

__device__ __forceinline__ void gemm_body(const float* __restrict__ A,
                                          const float* __restrict__ W,
                                          const float* __restrict__ bias,
                                          float* __restrict__ C)
{
    __shared__ float sm[2 * BUF_FLOATS];
    const uint32_t smem_base = smem_to_u32(sm);
    const int tid = threadIdx.x;
    const int wid = tid >> 5, lane = tid & 31;
    const int g = lane >> 2, tq = lane & 3;
    const int wm = wid >> 2, wn = wid & 3;       // 2 x 4 warp grid
    const int m0 = blockIdx.y * 128, n0 = blockIdx.x * 128;

    float acc[4][4][4];
#pragma unroll
    for (int mt = 0; mt < 4; mt++)
#pragma unroll
        for (int nt = 0; nt < 4; nt++)
#pragma unroll
            for (int r = 0; r < 4; r++) acc[mt][nt][r] = 0.f;

    gemm_prefetch(A, W, m0, n0, 0, smem_base, smem_base + ABYTES, tid);

    int buf = 0;
#pragma unroll 1
    for (int s = 0; s < FEATC / BKt; s++) {
        if (s + 1 < FEATC / BKt) {
            uint32_t base = smem_base + (buf ^ 1) * (ABYTES + BBYTES);
            gemm_prefetch(A, W, m0, n0, s + 1, base, base + ABYTES, tid);
            CP_WAIT(1);
        } else {
            CP_WAIT(0);
        }
        __syncthreads();

        const float* As = sm + buf * BUF_FLOATS;
        const float* Bs = As + ABYTES / 4;

#pragma unroll
        for (int ks = 0; ks < 2; ks++) {
            // B fragments (hi/lo split), all 4 n-tiles
            uint32_t bh[4][2], bl[4][2];
#pragma unroll
            for (int nt = 0; nt < 4; nt++) {
                int n = wn * 32 + nt * 8 + g;
                float b0 = Bs[(ks * 8 + tq) * BSTR + n];
                float b1 = Bs[(ks * 8 + tq + 4) * BSTR + n];
                float h0 = tf32_rna(b0), h1 = tf32_rna(b1);
                bh[nt][0] = __float_as_uint(h0);
                bh[nt][1] = __float_as_uint(h1);
                bl[nt][0] = __float_as_uint(tf32_rna(b0 - h0));
                bl[nt][1] = __float_as_uint(tf32_rna(b1 - h1));
            }
#pragma unroll
            for (int mt = 0; mt < 4; mt++) {
                int r = wm * 64 + mt * 16 + g;
                int c = ks * 8 + tq;
                float a0 = As[r * ASTR + c];
                float a1 = As[(r + 8) * ASTR + c];
                float a2 = As[r * ASTR + c + 4];
                float a3 = As[(r + 8) * ASTR + c + 4];
                float h0 = tf32_rna(a0), h1 = tf32_rna(a1);
                float h2 = tf32_rna(a2), h3 = tf32_rna(a3);
                uint32_t ah[4] = { __float_as_uint(h0), __float_as_uint(h1),
                                   __float_as_uint(h2), __float_as_uint(h3) };
                uint32_t al[4] = { __float_as_uint(tf32_rna(a0 - h0)),
                                   __float_as_uint(tf32_rna(a1 - h1)),
                                   __float_as_uint(tf32_rna(a2 - h2)),
                                   __float_as_uint(tf32_rna(a3 - h3)) };
#pragma unroll
                for (int nt = 0; nt < 4; nt++) {
                    mma8(acc[mt][nt], al, bh[nt]);   // a_lo * b_hi
                    mma8(acc[mt][nt], ah, bl[nt]);   // a_hi * b_lo
                    mma8(acc[mt][nt], ah, bh[nt]);   // a_hi * b_hi
                }
            }
        }
        __syncthreads();
        buf ^= 1;
    }

    // epilogue: direct global stores with bias
#pragma unroll
    for (int mt = 0; mt < 4; mt++) {
        int r = m0 + wm * 64 + mt * 16 + g;
#pragma unroll
        for (int nt = 0; nt < 4; nt++) {
            int cc = n0 + wn * 32 + nt * 8 + tq * 2;
            float bx = bias[cc], by = bias[cc + 1];
            float2 o0, o1;
            o0.x = acc[mt][nt][0] + bx; o0.y = acc[mt][nt][1] + by;
            o1.x = acc[mt][nt][2] + bx; o1.y = acc[mt][nt][3] + by;
            *(float2*)&C[(size_t)r * FEATC + cc]       = o0;
            *(float2*)&C[(size_t)(r + 8) * FEATC + cc] = o1;
        }
    }
}

__global__ __launch_bounds__(256, 1) void qkv_mma(const float* __restrict__ Q,
    const float* __restrict__ K, const float* __restrict__ V,
    const float* __restrict__ Wq, const float* __restrict__ Wk,
    const float* __restrict__ Wv,
    const float* __restrict__ bq, const float* __restrict__ bk,
    const float* __restrict__ bv)
{
    const int z = blockIdx.z;
    const float* A  = (z == 0) ? Q  : (z == 1) ? K  : V;
    const float* W  = (z == 0) ? Wq : (z == 1) ? Wk : Wv;
    const float* bi = (z == 0) ? bq : (z == 1) ? bk : bv;
    float*       C  = (z == 0) ? g_q : (z == 1) ? g_k : g_v;
    gemm_body(A, W, bi, C);
}

__global__ __launch_bounds__(256, 1) void out_mma(const float* __restrict__ Wo,
                                                  const float* __restrict__ bo,
                                                  float* __restrict__ out)
{
    gemm_body(g_x, Wo, bo, out);
}

// ---------------- banded attention with adaptive soft span ----------------
__global__ __launch_bounds__(256) void attn_kernel(const int* __restrict__ mask,
                                                   const float* __restrict__ span)
{
    extern __shared__ float smema[];
    float* Ks = smema;                  // KR*KSTR
    float* Vs = Ks + KR * KSTR;         // KR*KSTR
    float* Qs = Vs + KR * KSTR;         // 8*64
    float* Ws = Qs + 8 * 64;            // 8*SPANC
    int*   Ms = (int*)(Ws + 8 * SPANC); // KR

    const int tid  = threadIdx.x;
    const int w    = tid >> 5;
    const int lane = tid & 31;
    const int bh = blockIdx.y;
    const int b = bh >> 3, h = bh & 7;
    const int t0 = blockIdx.x * TQ;
    const int j0 = t0 - PADL;

    const size_t baseHB = (size_t)b * TT * FEATC + h * DKc;

    for (int idx = tid; idx < KR * DKc; idx += 256) {
        int r = idx >> 6, d = idx & 63;
        int j = j0 + r;
        float kv = 0.f, vv = 0.f;
        if (j >= 0 && j < TT) {
            kv = g_k[baseHB + (size_t)j * FEATC + d];
            vv = g_v[baseHB + (size_t)j * FEATC + d];
        }
        Ks[r * KSTR + d] = kv;
        Vs[r * KSTR + d] = vv;
    }
    for (int idx = tid; idx < KR; idx += 256) {
        int j = j0 + idx;
        Ms[idx] = (j >= 0 && j < TT) ? mask[b * TT + j] : 0;
    }
    __syncthreads();

    const float sp = span[h];
    const float4* K4 = (const float4*)Ks;

    for (int qi = 0; qi < 4; qi++) {
        const int t = t0 + w * 4 + qi;
        const int qloc = t - t0;

        Qs[w * 64 + lane]      = g_q[baseHB + (size_t)t * FEATC + lane];
        Qs[w * 64 + 32 + lane] = g_q[baseHB + (size_t)t * FEATC + 32 + lane];
        __syncwarp();

        const int s0 = lane, s1 = lane + 32, s2 = lane + 64, s3 = lane + 96;
        const int r0 = qloc + s0, r1 = qloc + s1, r2 = qloc + s2;
        const bool ok3 = (s3 < SPANC);
        const int r3 = ok3 ? (qloc + s3) : r0;

        const float4* Q4  = (const float4*)(Qs + w * 64);
        const float4* pk0 = K4 + r0 * 17;
        const float4* pk1 = K4 + r1 * 17;
        const float4* pk2 = K4 + r2 * 17;
        const float4* pk3 = K4 + r3 * 17;

        float acc0 = 0.f, acc1 = 0.f, acc2 = 0.f, acc3 = 0.f;
#pragma unroll
        for (int d4 = 0; d4 < 16; d4++) {
            float4 q = Q4[d4];
            float4 k0v = pk0[d4];
            float4 k1v = pk1[d4];
            float4 k2v = pk2[d4];
            float4 k3v = pk3[d4];
            acc0 = fmaf(q.x, k0v.x, fmaf(q.y, k0v.y, fmaf(q.z, k0v.z, fmaf(q.w, k0v.w, acc0))));
            acc1 = fmaf(q.x, k1v.x, fmaf(q.y, k1v.y, fmaf(q.z, k1v.z, fmaf(q.w, k1v.w, acc1))));
            acc2 = fmaf(q.x, k2v.x, fmaf(q.y, k2v.y, fmaf(q.z, k2v.z, fmaf(q.w, k2v.w, acc2))));
            acc3 = fmaf(q.x, k3v.x, fmaf(q.y, k3v.y, fmaf(q.z, k3v.z, fmaf(q.w, k3v.w, acc3))));
        }

        const float scale = 0.125f;
        const bool v0 = Ms[r0] != 0;
        const bool v1 = Ms[r1] != 0;
        const bool v2 = Ms[r2] != 0;
        const bool v3 = ok3 && (Ms[r3] != 0);
        float sc0 = acc0 * scale, sc1 = acc1 * scale, sc2 = acc2 * scale, sc3 = acc3 * scale;

        float x0 = v0 ? sc0 : -1e30f;
        float x1 = v1 ? sc1 : -1e30f;
        float x2 = v2 ? sc2 : -1e30f;
        float x3 = v3 ? sc3 : -1e30f;
        float mx = fmaxf(fmaxf(x0, x1), fmaxf(x2, x3));
#pragma unroll
        for (int o = 16; o; o >>= 1) mx = fmaxf(mx, __shfl_xor_sync(0xffffffffu, mx, o));

        float e0 = v0 ? __expf(sc0 - mx) : 0.f;
        float e1 = v1 ? __expf(sc1 - mx) : 0.f;
        float e2 = v2 ? __expf(sc2 - mx) : 0.f;
        float e3 = v3 ? __expf(sc3 - mx) : 0.f;

        float so0 = fminf(fmaxf(((float)(s0 - 99) + sp * 100.f) * 0.5f + 1.f, 0.f), 1.f);
        float so1 = fminf(fmaxf(((float)(s1 - 99) + sp * 100.f) * 0.5f + 1.f, 0.f), 1.f);
        float so2 = fminf(fmaxf(((float)(s2 - 99) + sp * 100.f) * 0.5f + 1.f, 0.f), 1.f);
        float so3 = fminf(fmaxf(((float)(s3 - 99) + sp * 100.f) * 0.5f + 1.f, 0.f), 1.f);

        float a0 = e0 * so0, a1 = e1 * so1, a2 = e2 * so2, a3 = e3 * so3;
        float E  = e0 + e1 + e2 + e3;
        float Sa = a0 + a1 + a2 + a3;
#pragma unroll
        for (int o = 16; o; o >>= 1) {
            E  += __shfl_xor_sync(0xffffffffu, E,  o);
            Sa += __shfl_xor_sync(0xffffffffu, Sa, o);
        }
        const float inv = 1.f / (Sa + 1e-8f * E);

        Ws[w * SPANC + s0] = a0 * inv;
        Ws[w * SPANC + s1] = a1 * inv;
        Ws[w * SPANC + s2] = a2 * inv;
        if (ok3) Ws[w * SPANC + s3] = a3 * inv;
        __syncwarp();

        // PV: lanes split DK in float2 (lane -> dims 2*lane, 2*lane+1)
        float o0 = 0.f, o1 = 0.f;
        const float* wrow = Ws + w * SPANC;
        const float2* vrow2 = (const float2*)(Vs + qloc * KSTR);
#pragma unroll 4
        for (int s = 0; s < SPANC; s++) {
            float wt = wrow[s];
            float2 vv = vrow2[s * 34 + lane];
            o0 = fmaf(wt, vv.x, o0);
            o1 = fmaf(wt, vv.y, o1);
        }
        float2 ov; ov.x = o0; ov.y = o1;
        *(float2*)&g_x[baseHB + (size_t)t * FEATC + 2 * lane] = ov;
        __syncwarp();
    }
}

// ---------------- launch ----------------
extern "C" void kernel_launch(void* const* d_in, const int* in_sizes, int n_in,
                              void* d_out, int out_size)
{
    const float* query = (const float*)d_in[0];
    const float* key   = (const float*)d_in[1];
    const float* value = (const float*)d_in[2];
    const int*   mask  = (const int*)d_in[3];
    const float* Wq    = (const float*)d_in[4];
    const float* bq    = (const float*)d_in[5];
    const float* Wk    = (const float*)d_in[6];
    const float* bk    = (const float*)d_in[7];
    const float* Wv    = (const float*)d_in[8];
    const float* bv    = (const float*)d_in[9];
    const float* Wo    = (const float*)d_in[10];
    const float* bo    = (const float*)d_in[11];
    const float* span  = (const float*)d_in[12];
    float* out = (float*)d_out;

    // QKV projections (3x tensor-core GEMM in one launch)
    qkv_mma<<<dim3(FEATC / 128, (BB * TT) / 128, 3), 256>>>(
        query, key, value, Wq, Wk, Wv, bq, bk, bv);

    // banded attention
    size_t smem = (size_t)(2 * KR * KSTR + 8 * 64 + 8 * SPANC) * sizeof(float)
                + (size_t)KR * sizeof(int);
    cudaFuncSetAttribute(attn_kernel, cudaFuncAttributeMaxDynamicSharedMemorySize, (int)smem);
    attn_kernel<<<dim3(TT / TQ, BB * HH), 256, smem>>>(mask, span);

    // output projection
    out_mma<<<dim3(FEATC / 128, (BB * TT) / 128), 256>>>(Wo, bo, out);
}

// round 11
// speedup vs baseline: 1.6264x; 1.3280x over previous
#include <cuda_runtime.h>
#include <cuda_bf16.h>
#include <math.h>
#include <stdint.h>

#define BB    4
#define TT    1024
#define FEATC 512
#define HH    8
#define DKc   64
#define SPANC 100
#define PADL  50
#define TQ    32
#define KR    (TQ + SPANC - 1)   /* 131 */
#define KSTR  68                 /* padded row stride (floats) */
#define MTOT  (BB*TT)            /* 4096 */

// -------- scratch (device globals; no runtime allocation) --------
__device__ float g_q[MTOT*FEATC];
__device__ float g_k[MTOT*FEATC];
__device__ float g_v[MTOT*FEATC];
__device__ __nv_bfloat16 g_inh[3*MTOT*FEATC];   // split inputs hi [z][m][k]
__device__ __nv_bfloat16 g_inl[3*MTOT*FEATC];   // split inputs lo
__device__ __nv_bfloat16 g_wht[4*FEATC*FEATC];  // weights hi, transposed [z][n][k]
__device__ __nv_bfloat16 g_wlt[4*FEATC*FEATC];  // weights lo, transposed
__device__ __nv_bfloat16 g_xh[MTOT*FEATC];      // attention output hi [m][k]
__device__ __nv_bfloat16 g_xl[MTOT*FEATC];      // attention output lo

// ======================= helpers =======================
__device__ __forceinline__ void cp_async16(uint32_t dst, const void* src) {
    asm volatile("cp.async.cg.shared.global [%0], [%1], 16;" :: "r"(dst), "l"(src));
}
#define CP_COMMIT() asm volatile("cp.async.commit_group;" ::: "memory")
#define CP_WAIT(n)  asm volatile("cp.async.wait_group %0;" :: "n"(n) : "memory")

__device__ __forceinline__ uint32_t smem_to_u32(const void* p) {
    uint32_t a;
    asm("{ .reg .u64 t; cvta.to.shared.u64 t, %1; cvt.u32.u64 %0, t; }" : "=r"(a) : "l"(p));
    return a;
}

// D(16x8) += A(16x16) * B(16x8), bf16 inputs, fp32 accum. row.col.
__device__ __forceinline__ void mma16(float* c, const uint32_t* a, const uint32_t* b) {
    asm volatile(
        "mma.sync.aligned.m16n8k16.row.col.f32.bf16.bf16.f32 "
        "{%0,%1,%2,%3},{%4,%5,%6,%7},{%8,%9},{%0,%1,%2,%3};"
        : "+f"(c[0]), "+f"(c[1]), "+f"(c[2]), "+f"(c[3])
        : "r"(a[0]), "r"(a[1]), "r"(a[2]), "r"(a[3]), "r"(b[0]), "r"(b[1]));
}

// ================= prep: split inputs into bf16 hi/lo =================
__global__ __launch_bounds__(256) void split_in(const float* __restrict__ q,
                                                const float* __restrict__ k,
                                                const float* __restrict__ v)
{
    const int z = blockIdx.y;
    const float4* src = (const float4*)((z == 0) ? q : (z == 1) ? k : v);
    int i = blockIdx.x * 256 + threadIdx.x;            // < MTOT*FEATC/4
    float4 a = src[i];
    size_t base = (size_t)z * (MTOT * FEATC) + (size_t)i * 4;

    __nv_bfloat16 h0 = __float2bfloat16(a.x), h1 = __float2bfloat16(a.y);
    __nv_bfloat16 h2 = __float2bfloat16(a.z), h3 = __float2bfloat16(a.w);
    __nv_bfloat16 l0 = __float2bfloat16(a.x - __bfloat162float(h0));
    __nv_bfloat16 l1 = __float2bfloat16(a.y - __bfloat162float(h1));
    __nv_bfloat16 l2 = __float2bfloat16(a.z - __bfloat162float(h2));
    __nv_bfloat16 l3 = __float2bfloat16(a.w - __bfloat162float(h3));

    *(__nv_bfloat162*)&g_inh[base]     = __halves2bfloat162(h0, h1);
    *(__nv_bfloat162*)&g_inh[base + 2] = __halves2bfloat162(h2, h3);
    *(__nv_bfloat162*)&g_inl[base]     = __halves2bfloat162(l0, l1);
    *(__nv_bfloat162*)&g_inl[base + 2] = __halves2bfloat162(l2, l3);
}

// ================= prep: split + transpose weights =================
__global__ void split_w(const float* __restrict__ W0, const float* __restrict__ W1,
                        const float* __restrict__ W2, const float* __restrict__ W3)
{
    __shared__ float t[32][33];
    const int z = blockIdx.z;
    const float* src = (z == 0) ? W0 : (z == 1) ? W1 : (z == 2) ? W2 : W3;
    const size_t zoff = (size_t)z * FEATC * FEATC;
    const int tx = threadIdx.x, ty = threadIdx.y;
    int n = blockIdx.x * 32 + tx;
    int k = blockIdx.y * 32 + ty;
#pragma unroll
    for (int i = 0; i < 32; i += 8)
        t[ty + i][tx] = src[(size_t)(k + i) * FEATC + n];
    __syncthreads();
    int k2 = blockIdx.y * 32 + tx;
    int n2 = blockIdx.x * 32 + ty;
#pragma unroll
    for (int i = 0; i < 32; i += 8) {
        float v = t[tx][ty + i];
        __nv_bfloat16 h = __float2bfloat16(v);
        __nv_bfloat16 l = __float2bfloat16(v - __bfloat162float(h));
        size_t dst = zoff + (size_t)(n2 + i) * FEATC + k2;
        g_wht[dst] = h;
        g_wlt[dst] = l;
    }
}

// ================= bf16x3 mma GEMM: C[M,512] = (Ah+Al) @ (Wh+Wl)^T + bias =================
// tile 128x128, BK=32 halfs, 8 warps (2x4), warp tile 64x32, cp.async double buffer
#define BKH   32
#define TSTRH 40                       /* padded row stride in halfs (20 b32) */
#define MAT_BYTES (128 * TSTRH * 2)    /* 10240 per matrix tile */
#define BUF_BYTES (4 * MAT_BYTES)      /* 40960 per buffer */
#define AH_B 0
#define AL_B (MAT_BYTES)
#define WH_B (2 * MAT_BYTES)
#define WL_B (3 * MAT_BYTES)
#define SMEM_GEMM (2 * BUF_BYTES)      /* 81920 */

__device__ __forceinline__ void prefetch_bf16(const __nv_bfloat16* __restrict__ Ah,
                                              const __nv_bfloat16* __restrict__ Al,
                                              const __nv_bfloat16* __restrict__ Wh,
                                              const __nv_bfloat16* __restrict__ Wl,
                                              int m0, int n0, int k0,
                                              uint32_t base, int tid)
{
#pragma unroll
    for (int i = 0; i < 2; i++) {
        int c = tid + i * 256;                 // 0..511 16B chunks per matrix
        int row = c >> 2, seg = c & 3;
        uint32_t o = (uint32_t)(row * (TSTRH * 2) + seg * 16);
        size_t ga = (size_t)(m0 + row) * FEATC + k0 + seg * 8;
        size_t gw = (size_t)(n0 + row) * FEATC + k0 + seg * 8;
        cp_async16(base + AH_B + o, Ah + ga);
        cp_async16(base + AL_B + o, Al + ga);
        cp_async16(base + WH_B + o, Wh + gw);
        cp_async16(base + WL_B + o, Wl + gw);
    }
    CP_COMMIT();
}

__device__ __forceinline__ void gemm_bf16_body(const __nv_bfloat16* __restrict__ Ah,
                                               const __nv_bfloat16* __restrict__ Al,
                                               const __nv_bfloat16* __restrict__ Wh,
                                               const __nv_bfloat16* __restrict__ Wl,
                                               const float* __restrict__ bias,
                                               float* __restrict__ C)
{
    extern __shared__ char smem[];
    const uint32_t smem_base = smem_to_u32(smem);
    const int tid = threadIdx.x;
    const int wid = tid >> 5, lane = tid & 31;
    const int g = lane >> 2, tq = lane & 3;
    const int wm = wid >> 2, wn = wid & 3;       // 2 x 4 warp grid
    const int m0 = blockIdx.y * 128, n0 = blockIdx.x * 128;

    float acc[4][4][4];
#pragma unroll
    for (int mt = 0; mt < 4; mt++)
#pragma unroll
        for (int nt = 0; nt < 4; nt++)
#pragma unroll
            for (int r = 0; r < 4; r++) acc[mt][nt][r] = 0.f;

    prefetch_bf16(Ah, Al, Wh, Wl, m0, n0, 0, smem_base, tid);

    int buf = 0;
#pragma unroll 1
    for (int s = 0; s < FEATC / BKH; s++) {
        if (s + 1 < FEATC / BKH) {
            prefetch_bf16(Ah, Al, Wh, Wl, m0, n0, (s + 1) * BKH,
                          smem_base + (buf ^ 1) * BUF_BYTES, tid);
            CP_WAIT(1);
        } else {
            CP_WAIT(0);
        }
        __syncthreads();

        const uint32_t* S  = (const uint32_t*)(smem + buf * BUF_BYTES);
        const uint32_t* A32h = S;
        const uint32_t* A32l = S + MAT_BYTES / 4;
        const uint32_t* W32h = S + 2 * (MAT_BYTES / 4);
        const uint32_t* W32l = S + 3 * (MAT_BYTES / 4);

#pragma unroll
        for (int ks = 0; ks < 2; ks++) {
            const int kb = ks * 8 + tq;            // b32 column within row
            uint32_t bh[4][2], bl[4][2];
#pragma unroll
            for (int nt = 0; nt < 4; nt++) {
                int n = wn * 32 + nt * 8 + g;
                bh[nt][0] = W32h[n * 20 + kb];
                bh[nt][1] = W32h[n * 20 + kb + 4];
                bl[nt][0] = W32l[n * 20 + kb];
                bl[nt][1] = W32l[n * 20 + kb + 4];
            }
#pragma unroll
            for (int mt = 0; mt < 4; mt++) {
                int r = wm * 64 + mt * 16 + g;
                uint32_t ah[4], al[4];
                ah[0] = A32h[r * 20 + kb];
                ah[1] = A32h[(r + 8) * 20 + kb];
                ah[2] = A32h[r * 20 + kb + 4];
                ah[3] = A32h[(r + 8) * 20 + kb + 4];
                al[0] = A32l[r * 20 + kb];
                al[1] = A32l[(r + 8) * 20 + kb];
                al[2] = A32l[r * 20 + kb + 4];
                al[3] = A32l[(r + 8) * 20 + kb + 4];
#pragma unroll
                for (int nt = 0; nt < 4; nt++) {
                    mma16(acc[mt][nt], ah, bh[nt]);   // a_hi * b_hi
                    mma16(acc[mt][nt], al, bh[nt]);   // a_lo * b_hi
                    mma16(acc[mt][nt], ah, bl[nt]);   // a_hi * b_lo
                }
            }
        }
        __syncthreads();
        buf ^= 1;
    }

    // epilogue: direct global stores with bias
#pragma unroll
    for (int mt = 0; mt < 4; mt++) {
        int r = m0 + wm * 64 + mt * 16 + g;
#pragma unroll
        for (int nt = 0; nt < 4; nt++) {
            int cc = n0 + wn * 32 + nt * 8 + tq * 2;
            float bx = bias[cc], by = bias[cc + 1];
            float2 o0, o1;
            o0.x = acc[mt][nt][0] + bx; o0.y = acc[mt][nt][1] + by;
            o1.x = acc[mt][nt][2] + bx; o1.y = acc[mt][nt][3] + by;
            *(float2*)&C[(size_t)r * FEATC + cc]       = o0;
            *(float2*)&C[(size_t)(r + 8) * FEATC + cc] = o1;
        }
    }
}

__global__ __launch_bounds__(256, 2) void qkv_bf16(const float* __restrict__ bq,
                                                   const float* __restrict__ bk,
                                                   const float* __restrict__ bv)
{
    const int z = blockIdx.z;
    const size_t izoff = (size_t)z * MTOT * FEATC;
    const size_t wzoff = (size_t)z * FEATC * FEATC;
    const float* bi = (z == 0) ? bq : (z == 1) ? bk : bv;
    float*       C  = (z == 0) ? g_q : (z == 1) ? g_k : g_v;
    gemm_bf16_body(g_inh + izoff, g_inl + izoff, g_wht + wzoff, g_wlt + wzoff, bi, C);
}

__global__ __launch_bounds__(256, 2) void out_bf16(const float* __restrict__ bo,
                                                   float* __restrict__ out)
{
    const size_t wzoff = (size_t)3 * FEATC * FEATC;
    gemm_bf16_body(g_xh, g_xl, g_wht + wzoff, g_wlt + wzoff, bo, out);
}

// ---------------- banded attention with adaptive soft span ----------------
__global__ __launch_bounds__(256) void attn_kernel(const int* __restrict__ mask,
                                                   const float* __restrict__ span)
{
    extern __shared__ float smema[];
    float* Ks = smema;                  // KR*KSTR
    float* Vs = Ks + KR * KSTR;         // KR*KSTR
    float* Qs = Vs + KR * KSTR;         // 8*64
    float* Ws = Qs + 8 * 64;            // 8*SPANC
    int*   Ms = (int*)(Ws + 8 * SPANC); // KR

    const int tid  = threadIdx.x;
    const int w    = tid >> 5;
    const int lane = tid & 31;
    const int bh = blockIdx.y;
    const int b = bh >> 3, h = bh & 7;
    const int t0 = blockIdx.x * TQ;
    const int j0 = t0 - PADL;

    const size_t baseHB = (size_t)b * TT * FEATC + h * DKc;

    for (int idx = tid; idx < KR * DKc; idx += 256) {
        int r = idx >> 6, d = idx & 63;
        int j = j0 + r;
        float kv = 0.f, vv = 0.f;
        if (j >= 0 && j < TT) {
            kv = g_k[baseHB + (size_t)j * FEATC + d];
            vv = g_v[baseHB + (size_t)j * FEATC + d];
        }
        Ks[r * KSTR + d] = kv;
        Vs[r * KSTR + d] = vv;
    }
    for (int idx = tid; idx < KR; idx += 256) {
        int j = j0 + idx;
        Ms[idx] = (j >= 0 && j < TT) ? mask[b * TT + j] : 0;
    }
    __syncthreads();

    const float sp = span[h];
    const float4* K4 = (const float4*)Ks;

    for (int qi = 0; qi < 4; qi++) {
        const int t = t0 + w * 4 + qi;
        const int qloc = t - t0;

        Qs[w * 64 + lane]      = g_q[baseHB + (size_t)t * FEATC + lane];
        Qs[w * 64 + 32 + lane] = g_q[baseHB + (size_t)t * FEATC + 32 + lane];
        __syncwarp();

        const int s0 = lane, s1 = lane + 32, s2 = lane + 64, s3 = lane + 96;
        const int r0 = qloc + s0, r1 = qloc + s1, r2 = qloc + s2;
        const bool ok3 = (s3 < SPANC);
        const int r3 = ok3 ? (qloc + s3) : r0;

        const float4* Q4  = (const float4*)(Qs + w * 64);
        const float4* pk0 = K4 + r0 * 17;
        const float4* pk1 = K4 + r1 * 17;
        const float4* pk2 = K4 + r2 * 17;
        const float4* pk3 = K4 + r3 * 17;

        float acc0 = 0.f, acc1 = 0.f, acc2 = 0.f, acc3 = 0.f;
#pragma unroll
        for (int d4 = 0; d4 < 16; d4++) {
            float4 q = Q4[d4];
            float4 k0v = pk0[d4];
            float4 k1v = pk1[d4];
            float4 k2v = pk2[d4];
            float4 k3v = pk3[d4];
            acc0 = fmaf(q.x, k0v.x, fmaf(q.y, k0v.y, fmaf(q.z, k0v.z, fmaf(q.w, k0v.w, acc0))));
            acc1 = fmaf(q.x, k1v.x, fmaf(q.y, k1v.y, fmaf(q.z, k1v.z, fmaf(q.w, k1v.w, acc1))));
            acc2 = fmaf(q.x, k2v.x, fmaf(q.y, k2v.y, fmaf(q.z, k2v.z, fmaf(q.w, k2v.w, acc2))));
            acc3 = fmaf(q.x, k3v.x, fmaf(q.y, k3v.y, fmaf(q.z, k3v.z, fmaf(q.w, k3v.w, acc3))));
        }

        const float scale = 0.125f;
        const bool v0 = Ms[r0] != 0;
        const bool v1 = Ms[r1] != 0;
        const bool v2 = Ms[r2] != 0;
        const bool v3 = ok3 && (Ms[r3] != 0);
        float sc0 = acc0 * scale, sc1 = acc1 * scale, sc2 = acc2 * scale, sc3 = acc3 * scale;

        float x0 = v0 ? sc0 : -1e30f;
        float x1 = v1 ? sc1 : -1e30f;
        float x2 = v2 ? sc2 : -1e30f;
        float x3 = v3 ? sc3 : -1e30f;
        float mx = fmaxf(fmaxf(x0, x1), fmaxf(x2, x3));
#pragma unroll
        for (int o = 16; o; o >>= 1) mx = fmaxf(mx, __shfl_xor_sync(0xffffffffu, mx, o));

        float e0 = v0 ? __expf(sc0 - mx) : 0.f;
        float e1 = v1 ? __expf(sc1 - mx) : 0.f;
        float e2 = v2 ? __expf(sc2 - mx) : 0.f;
        float e3 = v3 ? __expf(sc3 - mx) : 0.f;

        float so0 = fminf(fmaxf(((float)(s0 - 99) + sp * 100.f) * 0.5f + 1.f, 0.f), 1.f);
        float so1 = fminf(fmaxf(((float)(s1 - 99) + sp * 100.f) * 0.5f + 1.f, 0.f), 1.f);
        float so2 = fminf(fmaxf(((float)(s2 - 99) + sp * 100.f) * 0.5f + 1.f, 0.f), 1.f);
        float so3 = fminf(fmaxf(((float)(s3 - 99) + sp * 100.f) * 0.5f + 1.f, 0.f), 1.f);

        float a0 = e0 * so0, a1 = e1 * so1, a2 = e2 * so2, a3 = e3 * so3;
        float E  = e0 + e1 + e2 + e3;
        float Sa = a0 + a1 + a2 + a3;
#pragma unroll
        for (int o = 16; o; o >>= 1) {
            E  += __shfl_xor_sync(0xffffffffu, E,  o);
            Sa += __shfl_xor_sync(0xffffffffu, Sa, o);
        }
        const float inv = 1.f / (Sa + 1e-8f * E);

        Ws[w * SPANC + s0] = a0 * inv;
        Ws[w * SPANC + s1] = a1 * inv;
        Ws[w * SPANC + s2] = a2 * inv;
        if (ok3) Ws[w * SPANC + s3] = a3 * inv;
        __syncwarp();

        // PV: lanes split DK in float2 (lane -> dims 2*lane, 2*lane+1)
        float o0 = 0.f, o1 = 0.f;
        const float* wrow = Ws + w * SPANC;
        const float2* vrow2 = (const float2*)(Vs + qloc * KSTR);
#pragma unroll 4
        for (int s = 0; s < SPANC; s++) {
            float wt = wrow[s];
            float2 vv = vrow2[s * 34 + lane];
            o0 = fmaf(wt, vv.x, o0);
            o1 = fmaf(wt, vv.y, o1);
        }
        // write x as bf16 hi/lo split (feeds out_bf16 GEMM directly)
        __nv_bfloat16 h0 = __float2bfloat16(o0);
        __nv_bfloat16 l0 = __float2bfloat16(o0 - __bfloat162float(h0));
        __nv_bfloat16 h1 = __float2bfloat16(o1);
        __nv_bfloat16 l1 = __float2bfloat16(o1 - __bfloat162float(h1));
        size_t oidx = baseHB + (size_t)t * FEATC + 2 * lane;
        *(__nv_bfloat162*)&g_xh[oidx] = __halves2bfloat162(h0, h1);
        *(__nv_bfloat162*)&g_xl[oidx] = __halves2bfloat162(l0, l1);
        __syncwarp();
    }
}

// ---------------- launch ----------------
extern "C" void kernel_launch(void* const* d_in, const int* in_sizes, int n_in,
                              void* d_out, int out_size)
{
    const float* query = (const float*)d_in[0];
    const float* key   = (const float*)d_in[1];
    const float* value = (const float*)d_in[2];
    const int*   mask  = (const int*)d_in[3];
    const float* Wq    = (const float*)d_in[4];
    const float* bq    = (const float*)d_in[5];
    const float* Wk    = (const float*)d_in[6];
    const float* bk    = (const float*)d_in[7];
    const float* Wv    = (const float*)d_in[8];
    const float* bv    = (const float*)d_in[9];
    const float* Wo    = (const float*)d_in[10];
    const float* bo    = (const float*)d_in[11];
    const float* span  = (const float*)d_in[12];
    float* out = (float*)d_out;

    // prep: split inputs + split/transpose weights into bf16 hi/lo
    split_in<<<dim3(MTOT * FEATC / 4 / 256, 3), 256>>>(query, key, value);
    split_w<<<dim3(16, 16, 4), dim3(32, 8)>>>(Wq, Wk, Wv, Wo);

    cudaFuncSetAttribute(qkv_bf16, cudaFuncAttributeMaxDynamicSharedMemorySize, SMEM_GEMM);
    cudaFuncSetAttribute(out_bf16, cudaFuncAttributeMaxDynamicSharedMemorySize, SMEM_GEMM);

    // QKV projections (3 tensor-core GEMMs in one launch)
    qkv_bf16<<<dim3(FEATC / 128, MTOT / 128, 3), 256, SMEM_GEMM>>>(bq, bk, bv);

    // banded attention (writes x as bf16 hi/lo)
    size_t smem = (size_t)(2 * KR * KSTR + 8 * 64 + 8 * SPANC) * sizeof(float)
                + (size_t)KR * sizeof(int);
    cudaFuncSetAttribute(attn_kernel, cudaFuncAttributeMaxDynamicSharedMemorySize, (int)smem);
    attn_kernel<<<dim3(TT / TQ, BB * HH), 256, smem>>>(mask, span);

    // output projection
    out_bf16<<<dim3(FEATC / 128, MTOT / 128), 256, SMEM_GEMM>>>(bo, out);
}

// round 14
// speedup vs baseline: 1.7186x; 1.0567x over previous
#include <cuda_runtime.h>
#include <cuda_bf16.h>
#include <math.h>
#include <stdint.h>

#define BB    4
#define TT    1024
#define FEATC 512
#define HH    8
#define DKc   64
#define SPANC 100
#define PADL  50
#define TQ    32
#define KR    (TQ + SPANC - 1)   /* 131 */
#define KSTR  68                 /* padded row stride (floats) */
#define MTOT  (BB*TT)            /* 4096 */
#define ATH   512                /* attn threads per block */
#define AWARPS (ATH/32)          /* 16 */

// -------- scratch (device globals; no runtime allocation) --------
__device__ float g_q[MTOT*FEATC];
__device__ float g_k[MTOT*FEATC];
__device__ float g_v[MTOT*FEATC];
__device__ __nv_bfloat16 g_inh[3*MTOT*FEATC];   // split inputs hi [z][m][k]
__device__ __nv_bfloat16 g_inl[3*MTOT*FEATC];   // split inputs lo
__device__ __nv_bfloat16 g_wht[4*FEATC*FEATC];  // weights hi, transposed [z][n][k]
__device__ __nv_bfloat16 g_wlt[4*FEATC*FEATC];  // weights lo, transposed
__device__ __nv_bfloat16 g_xh[MTOT*FEATC];      // attention output hi [m][k]
__device__ __nv_bfloat16 g_xl[MTOT*FEATC];      // attention output lo

// ======================= helpers =======================
__device__ __forceinline__ void cp_async16(uint32_t dst, const void* src) {
    asm volatile("cp.async.cg.shared.global [%0], [%1], 16;" :: "r"(dst), "l"(src));
}
#define CP_COMMIT() asm volatile("cp.async.commit_group;" ::: "memory")
#define CP_WAIT(n)  asm volatile("cp.async.wait_group %0;" :: "n"(n) : "memory")

__device__ __forceinline__ uint32_t smem_to_u32(const void* p) {
    uint32_t a;
    asm("{ .reg .u64 t; cvta.to.shared.u64 t, %1; cvt.u32.u64 %0, t; }" : "=r"(a) : "l"(p));
    return a;
}

// D(16x8) += A(16x16) * B(16x8), bf16 inputs, fp32 accum. row.col.
__device__ __forceinline__ void mma16(float* c, const uint32_t* a, const uint32_t* b) {
    asm volatile(
        "mma.sync.aligned.m16n8k16.row.col.f32.bf16.bf16.f32 "
        "{%0,%1,%2,%3},{%4,%5,%6,%7},{%8,%9},{%0,%1,%2,%3};"
        : "+f"(c[0]), "+f"(c[1]), "+f"(c[2]), "+f"(c[3])
        : "r"(a[0]), "r"(a[1]), "r"(a[2]), "r"(a[3]), "r"(b[0]), "r"(b[1]));
}

// ================= prep: split inputs into bf16 hi/lo =================
__global__ __launch_bounds__(256) void split_in(const float* __restrict__ q,
                                                const float* __restrict__ k,
                                                const float* __restrict__ v)
{
    const int z = blockIdx.y;
    const float4* src = (const float4*)((z == 0) ? q : (z == 1) ? k : v);
    int i = blockIdx.x * 256 + threadIdx.x;            // < MTOT*FEATC/4
    float4 a = src[i];
    size_t base = (size_t)z * (MTOT * FEATC) + (size_t)i * 4;

    __nv_bfloat16 h0 = __float2bfloat16(a.x), h1 = __float2bfloat16(a.y);
    __nv_bfloat16 h2 = __float2bfloat16(a.z), h3 = __float2bfloat16(a.w);
    __nv_bfloat16 l0 = __float2bfloat16(a.x - __bfloat162float(h0));
    __nv_bfloat16 l1 = __float2bfloat16(a.y - __bfloat162float(h1));
    __nv_bfloat16 l2 = __float2bfloat16(a.z - __bfloat162float(h2));
    __nv_bfloat16 l3 = __float2bfloat16(a.w - __bfloat162float(h3));

    *(__nv_bfloat162*)&g_inh[base]     = __halves2bfloat162(h0, h1);
    *(__nv_bfloat162*)&g_inh[base + 2] = __halves2bfloat162(h2, h3);
    *(__nv_bfloat162*)&g_inl[base]     = __halves2bfloat162(l0, l1);
    *(__nv_bfloat162*)&g_inl[base + 2] = __halves2bfloat162(l2, l3);
}

// ================= prep: split + transpose weights =================
__global__ void split_w(const float* __restrict__ W0, const float* __restrict__ W1,
                        const float* __restrict__ W2, const float* __restrict__ W3)
{
    __shared__ float t[32][33];
    const int z = blockIdx.z;
    const float* src = (z == 0) ? W0 : (z == 1) ? W1 : (z == 2) ? W2 : W3;
    const size_t zoff = (size_t)z * FEATC * FEATC;
    const int tx = threadIdx.x, ty = threadIdx.y;
    int n = blockIdx.x * 32 + tx;
    int k = blockIdx.y * 32 + ty;
#pragma unroll
    for (int i = 0; i < 32; i += 8)
        t[ty + i][tx] = src[(size_t)(k + i) * FEATC + n];
    __syncthreads();
    int k2 = blockIdx.y * 32 + tx;
    int n2 = blockIdx.x * 32 + ty;
#pragma unroll
    for (int i = 0; i < 32; i += 8) {
        float v = t[tx][ty + i];
        __nv_bfloat16 h = __float2bfloat16(v);
        __nv_bfloat16 l = __float2bfloat16(v - __bfloat162float(h));
        size_t dst = zoff + (size_t)(n2 + i) * FEATC + k2;
        g_wht[dst] = h;
        g_wlt[dst] = l;
    }
}

// ================= bf16x3 mma GEMM: C[M,512] = (Ah+Al) @ (Wh+Wl)^T + bias =================
// tile 128x128, BK=32 halfs, 8 warps (2x4), warp tile 64x32, cp.async double buffer
#define BKH   32
#define TSTRH 40                       /* padded row stride in halfs (20 b32) */
#define MAT_BYTES (128 * TSTRH * 2)    /* 10240 per matrix tile */
#define BUF_BYTES (4 * MAT_BYTES)      /* 40960 per buffer */
#define AH_B 0
#define AL_B (MAT_BYTES)
#define WH_B (2 * MAT_BYTES)
#define WL_B (3 * MAT_BYTES)
#define SMEM_GEMM (2 * BUF_BYTES)      /* 81920 */

__device__ __forceinline__ void prefetch_bf16(const __nv_bfloat16* __restrict__ Ah,
                                              const __nv_bfloat16* __restrict__ Al,
                                              const __nv_bfloat16* __restrict__ Wh,
                                              const __nv_bfloat16* __restrict__ Wl,
                                              int m0, int n0, int k0,
                                              uint32_t base, int tid)
{
#pragma unroll
    for (int i = 0; i < 2; i++) {
        int c = tid + i * 256;                 // 0..511 16B chunks per matrix
        int row = c >> 2, seg = c & 3;
        uint32_t o = (uint32_t)(row * (TSTRH * 2) + seg * 16);
        size_t ga = (size_t)(m0 + row) * FEATC + k0 + seg * 8;
        size_t gw = (size_t)(n0 + row) * FEATC + k0 + seg * 8;
        cp_async16(base + AH_B + o, Ah + ga);
        cp_async16(base + AL_B + o, Al + ga);
        cp_async16(base + WH_B + o, Wh + gw);
        cp_async16(base + WL_B + o, Wl + gw);
    }
    CP_COMMIT();
}

__device__ __forceinline__ void gemm_bf16_body(const __nv_bfloat16* __restrict__ Ah,
                                               const __nv_bfloat16* __restrict__ Al,
                                               const __nv_bfloat16* __restrict__ Wh,
                                               const __nv_bfloat16* __restrict__ Wl,
                                               const float* __restrict__ bias,
                                               float* __restrict__ C)
{
    extern __shared__ char smem[];
    const uint32_t smem_base = smem_to_u32(smem);
    const int tid = threadIdx.x;
    const int wid = tid >> 5, lane = tid & 31;
    const int g = lane >> 2, tq = lane & 3;
    const int wm = wid >> 2, wn = wid & 3;       // 2 x 4 warp grid
    const int m0 = blockIdx.y * 128, n0 = blockIdx.x * 128;

    float acc[4][4][4];
#pragma unroll
    for (int mt = 0; mt < 4; mt++)
#pragma unroll
        for (int nt = 0; nt < 4; nt++)
#pragma unroll
            for (int r = 0; r < 4; r++) acc[mt][nt][r] = 0.f;

    prefetch_bf16(Ah, Al, Wh, Wl, m0, n0, 0, smem_base, tid);

    int buf = 0;
#pragma unroll 1
    for (int s = 0; s < FEATC / BKH; s++) {
        if (s + 1 < FEATC / BKH) {
            prefetch_bf16(Ah, Al, Wh, Wl, m0, n0, (s + 1) * BKH,
                          smem_base + (buf ^ 1) * BUF_BYTES, tid);
            CP_WAIT(1);
        } else {
            CP_WAIT(0);
        }
        __syncthreads();

        const uint32_t* S  = (const uint32_t*)(smem + buf * BUF_BYTES);
        const uint32_t* A32h = S;
        const uint32_t* A32l = S + MAT_BYTES / 4;
        const uint32_t* W32h = S + 2 * (MAT_BYTES / 4);
        const uint32_t* W32l = S + 3 * (MAT_BYTES / 4);

#pragma unroll
        for (int ks = 0; ks < 2; ks++) {
            const int kb = ks * 8 + tq;            // b32 column within row
            uint32_t bh[4][2], bl[4][2];
#pragma unroll
            for (int nt = 0; nt < 4; nt++) {
                int n = wn * 32 + nt * 8 + g;
                bh[nt][0] = W32h[n * 20 + kb];
                bh[nt][1] = W32h[n * 20 + kb + 4];
                bl[nt][0] = W32l[n * 20 + kb];
                bl[nt][1] = W32l[n * 20 + kb + 4];
            }
#pragma unroll
            for (int mt = 0; mt < 4; mt++) {
                int r = wm * 64 + mt * 16 + g;
                uint32_t ah[4], al[4];
                ah[0] = A32h[r * 20 + kb];
                ah[1] = A32h[(r + 8) * 20 + kb];
                ah[2] = A32h[r * 20 + kb + 4];
                ah[3] = A32h[(r + 8) * 20 + kb + 4];
                al[0] = A32l[r * 20 + kb];
                al[1] = A32l[(r + 8) * 20 + kb];
                al[2] = A32l[r * 20 + kb + 4];
                al[3] = A32l[(r + 8) * 20 + kb + 4];
#pragma unroll
                for (int nt = 0; nt < 4; nt++) {
                    mma16(acc[mt][nt], ah, bh[nt]);   // a_hi * b_hi
                    mma16(acc[mt][nt], al, bh[nt]);   // a_lo * b_hi
                    mma16(acc[mt][nt], ah, bl[nt]);   // a_hi * b_lo
                }
            }
        }
        __syncthreads();
        buf ^= 1;
    }

    // epilogue: direct global stores with bias
#pragma unroll
    for (int mt = 0; mt < 4; mt++) {
        int r = m0 + wm * 64 + mt * 16 + g;
#pragma unroll
        for (int nt = 0; nt < 4; nt++) {
            int cc = n0 + wn * 32 + nt * 8 + tq * 2;
            float bx = bias[cc], by = bias[cc + 1];
            float2 o0, o1;
            o0.x = acc[mt][nt][0] + bx; o0.y = acc[mt][nt][1] + by;
            o1.x = acc[mt][nt][2] + bx; o1.y = acc[mt][nt][3] + by;
            *(float2*)&C[(size_t)r * FEATC + cc]       = o0;
            *(float2*)&C[(size_t)(r + 8) * FEATC + cc] = o1;
        }
    }
}

__global__ __launch_bounds__(256, 2) void qkv_bf16(const float* __restrict__ bq,
                                                   const float* __restrict__ bk,
                                                   const float* __restrict__ bv)
{
    const int z = blockIdx.z;
    const size_t izoff = (size_t)z * MTOT * FEATC;
    const size_t wzoff = (size_t)z * FEATC * FEATC;
    const float* bi = (z == 0) ? bq : (z == 1) ? bk : bv;
    float*       C  = (z == 0) ? g_q : (z == 1) ? g_k : g_v;
    gemm_bf16_body(g_inh + izoff, g_inl + izoff, g_wht + wzoff, g_wlt + wzoff, bi, C);
}

__global__ __launch_bounds__(256, 2) void out_bf16(const float* __restrict__ bo,
                                                   float* __restrict__ out)
{
    const size_t wzoff = (size_t)3 * FEATC * FEATC;
    gemm_bf16_body(g_xh, g_xl, g_wht + wzoff, g_wlt + wzoff, bo, out);
}

// ---------------- banded attention with adaptive soft span ----------------
// 512 threads, 16 warps, 2 queries per warp; PV float4 with 2-span-parallel lanes
__global__ __launch_bounds__(ATH) void attn_kernel(const int* __restrict__ mask,
                                                   const float* __restrict__ span)
{
    extern __shared__ float smema[];
    float* Ks = smema;                       // KR*KSTR
    float* Vs = Ks + KR * KSTR;              // KR*KSTR
    float* Qs = Vs + KR * KSTR;              // AWARPS*64
    float* Ws = Qs + AWARPS * 64;            // AWARPS*SPANC
    int*   Ms = (int*)(Ws + AWARPS * SPANC); // KR

    const int tid  = threadIdx.x;
    const int w    = tid >> 5;
    const int lane = tid & 31;
    const int bh = blockIdx.y;
    const int b = bh >> 3, h = bh & 7;
    const int t0 = blockIdx.x * TQ;
    const int j0 = t0 - PADL;

    const size_t baseHB = (size_t)b * TT * FEATC + h * DKc;

    for (int idx = tid; idx < KR * DKc; idx += ATH) {
        int r = idx >> 6, d = idx & 63;
        int j = j0 + r;
        float kv = 0.f, vv = 0.f;
        if (j >= 0 && j < TT) {
            kv = g_k[baseHB + (size_t)j * FEATC + d];
            vv = g_v[baseHB + (size_t)j * FEATC + d];
        }
        Ks[r * KSTR + d] = kv;
        Vs[r * KSTR + d] = vv;
    }
    for (int idx = tid; idx < KR; idx += ATH) {
        int j = j0 + idx;
        Ms[idx] = (j >= 0 && j < TT) ? mask[b * TT + j] : 0;
    }
    __syncthreads();

    const float sp = span[h];
    const float4* K4 = (const float4*)Ks;

    for (int qi = 0; qi < 2; qi++) {
        const int qloc = w * 2 + qi;
        const int t = t0 + qloc;

        Qs[w * 64 + lane]      = g_q[baseHB + (size_t)t * FEATC + lane];
        Qs[w * 64 + 32 + lane] = g_q[baseHB + (size_t)t * FEATC + 32 + lane];
        __syncwarp();

        const int s0 = lane, s1 = lane + 32, s2 = lane + 64, s3 = lane + 96;
        const int r0 = qloc + s0, r1 = qloc + s1, r2 = qloc + s2;
        const bool ok3 = (s3 < SPANC);
        const int r3 = ok3 ? (qloc + s3) : r0;

        const float4* Q4  = (const float4*)(Qs + w * 64);
        const float4* pk0 = K4 + r0 * 17;
        const float4* pk1 = K4 + r1 * 17;
        const float4* pk2 = K4 + r2 * 17;
        const float4* pk3 = K4 + r3 * 17;

        float acc0 = 0.f, acc1 = 0.f, acc2 = 0.f, acc3 = 0.f;
#pragma unroll
        for (int d4 = 0; d4 < 16; d4++) {
            float4 q = Q4[d4];
            float4 k0v = pk0[d4];
            float4 k1v = pk1[d4];
            float4 k2v = pk2[d4];
            float4 k3v = pk3[d4];
            acc0 = fmaf(q.x, k0v.x, fmaf(q.y, k0v.y, fmaf(q.z, k0v.z, fmaf(q.w, k0v.w, acc0))));
            acc1 = fmaf(q.x, k1v.x, fmaf(q.y, k1v.y, fmaf(q.z, k1v.z, fmaf(q.w, k1v.w, acc1))));
            acc2 = fmaf(q.x, k2v.x, fmaf(q.y, k2v.y, fmaf(q.z, k2v.z, fmaf(q.w, k2v.w, acc2))));
            acc3 = fmaf(q.x, k3v.x, fmaf(q.y, k3v.y, fmaf(q.z, k3v.z, fmaf(q.w, k3v.w, acc3))));
        }

        const float scale = 0.125f;
        const bool v0 = Ms[r0] != 0;
        const bool v1 = Ms[r1] != 0;
        const bool v2 = Ms[r2] != 0;
        const bool v3 = ok3 && (Ms[r3] != 0);
        float sc0 = acc0 * scale, sc1 = acc1 * scale, sc2 = acc2 * scale, sc3 = acc3 * scale;

        float x0 = v0 ? sc0 : -1e30f;
        float x1 = v1 ? sc1 : -1e30f;
        float x2 = v2 ? sc2 : -1e30f;
        float x3 = v3 ? sc3 : -1e30f;
        float mx = fmaxf(fmaxf(x0, x1), fmaxf(x2, x3));
#pragma unroll
        for (int o = 16; o; o >>= 1) mx = fmaxf(mx, __shfl_xor_sync(0xffffffffu, mx, o));

        float e0 = v0 ? __expf(sc0 - mx) : 0.f;
        float e1 = v1 ? __expf(sc1 - mx) : 0.f;
        float e2 = v2 ? __expf(sc2 - mx) : 0.f;
        float e3 = v3 ? __expf(sc3 - mx) : 0.f;

        float so0 = fminf(fmaxf(((float)(s0 - 99) + sp * 100.f) * 0.5f + 1.f, 0.f), 1.f);
        float so1 = fminf(fmaxf(((float)(s1 - 99) + sp * 100.f) * 0.5f + 1.f, 0.f), 1.f);
        float so2 = fminf(fmaxf(((float)(s2 - 99) + sp * 100.f) * 0.5f + 1.f, 0.f), 1.f);
        float so3 = fminf(fmaxf(((float)(s3 - 99) + sp * 100.f) * 0.5f + 1.f, 0.f), 1.f);

        float a0 = e0 * so0, a1 = e1 * so1, a2 = e2 * so2, a3 = e3 * so3;
        float E  = e0 + e1 + e2 + e3;
        float Sa = a0 + a1 + a2 + a3;
#pragma unroll
        for (int o = 16; o; o >>= 1) {
            E  += __shfl_xor_sync(0xffffffffu, E,  o);
            Sa += __shfl_xor_sync(0xffffffffu, Sa, o);
        }
        const float inv = 1.f / (Sa + 1e-8f * E);

        Ws[w * SPANC + s0] = a0 * inv;
        Ws[w * SPANC + s1] = a1 * inv;
        Ws[w * SPANC + s2] = a2 * inv;
        if (ok3) Ws[w * SPANC + s3] = a3 * inv;
        __syncwarp();

        // PV: lane covers 4 dims, lane>>4 selects span parity; 50 iterations of LDS.128
        const int dl = (lane & 15) * 4;
        const int shp = lane >> 4;
        float o0 = 0.f, o1 = 0.f, o2 = 0.f, o3 = 0.f;
        const float* wrow = Ws + w * SPANC;
#pragma unroll 5
        for (int s = 0; s < SPANC; s += 2) {
            float wt = wrow[s + shp];
            float4 vv = *(const float4*)&Vs[(qloc + s + shp) * KSTR + dl];
            o0 = fmaf(wt, vv.x, o0);
            o1 = fmaf(wt, vv.y, o1);
            o2 = fmaf(wt, vv.z, o2);
            o3 = fmaf(wt, vv.w, o3);
        }
        o0 += __shfl_xor_sync(0xffffffffu, o0, 16);
        o1 += __shfl_xor_sync(0xffffffffu, o1, 16);
        o2 += __shfl_xor_sync(0xffffffffu, o2, 16);
        o3 += __shfl_xor_sync(0xffffffffu, o3, 16);

        if (lane < 16) {
            __nv_bfloat16 h0 = __float2bfloat16(o0);
            __nv_bfloat16 l0 = __float2bfloat16(o0 - __bfloat162float(h0));
            __nv_bfloat16 h1 = __float2bfloat16(o1);
            __nv_bfloat16 l1 = __float2bfloat16(o1 - __bfloat162float(h1));
            __nv_bfloat16 h2 = __float2bfloat16(o2);
            __nv_bfloat16 l2 = __float2bfloat16(o2 - __bfloat162float(h2));
            __nv_bfloat16 h3 = __float2bfloat16(o3);
            __nv_bfloat16 l3 = __float2bfloat16(o3 - __bfloat162float(h3));
            size_t oidx = baseHB + (size_t)t * FEATC + dl;
            *(__nv_bfloat162*)&g_xh[oidx]     = __halves2bfloat162(h0, h1);
            *(__nv_bfloat162*)&g_xh[oidx + 2] = __halves2bfloat162(h2, h3);
            *(__nv_bfloat162*)&g_xl[oidx]     = __halves2bfloat162(l0, l1);
            *(__nv_bfloat162*)&g_xl[oidx + 2] = __halves2bfloat162(l2, l3);
        }
        __syncwarp();
    }
}

// ---------------- launch ----------------
extern "C" void kernel_launch(void* const* d_in, const int* in_sizes, int n_in,
                              void* d_out, int out_size)
{
    const float* query = (const float*)d_in[0];
    const float* key   = (const float*)d_in[1];
    const float* value = (const float*)d_in[2];
    const int*   mask  = (const int*)d_in[3];
    const float* Wq    = (const float*)d_in[4];
    const float* bq    = (const float*)d_in[5];
    const float* Wk    = (const float*)d_in[6];
    const float* bk    = (const float*)d_in[7];
    const float* Wv    = (const float*)d_in[8];
    const float* bv    = (const float*)d_in[9];
    const float* Wo    = (const float*)d_in[10];
    const float* bo    = (const float*)d_in[11];
    const float* span  = (const float*)d_in[12];
    float* out = (float*)d_out;

    // prep: split inputs + split/transpose weights into bf16 hi/lo
    split_in<<<dim3(MTOT * FEATC / 4 / 256, 3), 256>>>(query, key, value);
    split_w<<<dim3(16, 16, 4), dim3(32, 8)>>>(Wq, Wk, Wv, Wo);

    cudaFuncSetAttribute(qkv_bf16, cudaFuncAttributeMaxDynamicSharedMemorySize, SMEM_GEMM);
    cudaFuncSetAttribute(out_bf16, cudaFuncAttributeMaxDynamicSharedMemorySize, SMEM_GEMM);

    // QKV projections (3 tensor-core GEMMs in one launch)
    qkv_bf16<<<dim3(FEATC / 128, MTOT / 128, 3), 256, SMEM_GEMM>>>(bq, bk, bv);

    // banded attention (writes x as bf16 hi/lo)
    size_t smem = (size_t)(2 * KR * KSTR + AWARPS * 64 + AWARPS * SPANC) * sizeof(float)
                + (size_t)KR * sizeof(int);
    cudaFuncSetAttribute(attn_kernel, cudaFuncAttributeMaxDynamicSharedMemorySize, (int)smem);
    attn_kernel<<<dim3(TT / TQ, BB * HH), ATH, smem>>>(mask, span);

    // output projection
    out_bf16<<<dim3(FEATC / 128, MTOT / 128), 256, SMEM_GEMM>>>(bo, out);
}